// round 1
// baseline (speedup 1.0000x reference)
#include <cuda_runtime.h>
#include <math.h>

// Problem constants
#define BB 8
#define LL 2048
#define EE 1024
#define HH 16
#define DD 64
#define MROWS (BB*LL)          // 16384
#define EPSF 1e-6f

// Scratch (device globals: allocation-free rule)
__device__ float g_q[(size_t)MROWS * EE];
__device__ float g_k[(size_t)MROWS * EE];
__device__ float g_v[(size_t)MROWS * EE];
__device__ float g_attn[(size_t)MROWS * EE];

// ---------------------------------------------------------------------------
// SGEMM: C = A(MxK) @ W(KxN) + bias, row-major. 128x128 block, 8x8/thread.
// blockIdx.z selects among up to 3 (W,bias,C) triples (fused QKV).
// ---------------------------------------------------------------------------
#define BM 128
#define BN 128
#define BKK 16

__global__ __launch_bounds__(256, 1) void sgemm3(
    const float* __restrict__ A,
    const float* __restrict__ W0, const float* __restrict__ b0, float* __restrict__ C0,
    const float* __restrict__ W1, const float* __restrict__ b1, float* __restrict__ C1,
    const float* __restrict__ W2, const float* __restrict__ b2, float* __restrict__ C2)
{
    constexpr int K = EE;
    constexpr int N = EE;
    const float* Wp = W0; const float* bp = b0; float* Cp = C0;
    if (blockIdx.z == 1) { Wp = W1; bp = b1; Cp = C1; }
    else if (blockIdx.z == 2) { Wp = W2; bp = b2; Cp = C2; }

    __shared__ float As[BKK][BM + 4];   // transposed A tile
    __shared__ float Bs[BKK][BN + 4];

    const int tid = threadIdx.x;
    const int tx = tid & 15;
    const int ty = tid >> 4;
    const long long brow = (long long)blockIdx.y * BM;
    const int bcol = blockIdx.x * BN;

    const float* Aptr = A + brow * K;
    const float* Bptr = Wp + bcol;

    float acc[8][8];
#pragma unroll
    for (int i = 0; i < 8; i++)
#pragma unroll
        for (int j = 0; j < 8; j++) acc[i][j] = 0.0f;

    for (int kt = 0; kt < K; kt += BKK) {
        // Load A tile (BM x BKK): 512 float4, 2 per thread; store transposed.
#pragma unroll
        for (int i = 0; i < 2; i++) {
            int idx = tid + i * 256;
            int r  = idx >> 2;      // 0..127
            int c4 = idx & 3;       // 0..3
            float4 v = *(const float4*)(Aptr + (long long)r * K + kt + c4 * 4);
            As[c4 * 4 + 0][r] = v.x;
            As[c4 * 4 + 1][r] = v.y;
            As[c4 * 4 + 2][r] = v.z;
            As[c4 * 4 + 3][r] = v.w;
        }
        // Load B tile (BKK x BN): 512 float4, 2 per thread.
#pragma unroll
        for (int i = 0; i < 2; i++) {
            int idx = tid + i * 256;
            int r  = idx >> 5;      // 0..15
            int c4 = idx & 31;      // 0..31
            float4 v = *(const float4*)(Bptr + (long long)(kt + r) * N + c4 * 4);
            *(float4*)&Bs[r][c4 * 4] = v;
        }
        __syncthreads();
#pragma unroll
        for (int k = 0; k < BKK; k++) {
            float ra[8], rb[8];
            *(float4*)&ra[0] = *(const float4*)&As[k][ty * 8];
            *(float4*)&ra[4] = *(const float4*)&As[k][ty * 8 + 4];
            *(float4*)&rb[0] = *(const float4*)&Bs[k][tx * 8];
            *(float4*)&rb[4] = *(const float4*)&Bs[k][tx * 8 + 4];
#pragma unroll
            for (int i = 0; i < 8; i++)
#pragma unroll
                for (int j = 0; j < 8; j++)
                    acc[i][j] = fmaf(ra[i], rb[j], acc[i][j]);
        }
        __syncthreads();
    }

    float4 bias0 = *(const float4*)(bp + bcol + tx * 8);
    float4 bias1 = *(const float4*)(bp + bcol + tx * 8 + 4);
#pragma unroll
    for (int i = 0; i < 8; i++) {
        long long r = brow + ty * 8 + i;
        float4 o0, o1;
        o0.x = acc[i][0] + bias0.x; o0.y = acc[i][1] + bias0.y;
        o0.z = acc[i][2] + bias0.z; o0.w = acc[i][3] + bias0.w;
        o1.x = acc[i][4] + bias1.x; o1.y = acc[i][5] + bias1.y;
        o1.z = acc[i][6] + bias1.z; o1.w = acc[i][7] + bias1.w;
        *(float4*)(Cp + r * N + bcol + tx * 8)     = o0;
        *(float4*)(Cp + r * N + bcol + tx * 8 + 4) = o1;
    }
}

// ---------------------------------------------------------------------------
// Row softmax over D=64 for q and k in place. One warp per 64-float row.
// Rows are contiguous: row r at offset r*64.
// ---------------------------------------------------------------------------
__global__ __launch_bounds__(256) void softmax_qk()
{
    const long long NR = (long long)BB * LL * HH;     // 262144 rows per tensor
    long long w = (((long long)blockIdx.x * blockDim.x) + threadIdx.x) >> 5;
    int lane = threadIdx.x & 31;
    if (w >= 2 * NR) return;
    float* row = (w < NR) ? (g_q + w * DD) : (g_k + (w - NR) * DD);

    float2 v = *(float2*)(row + lane * 2);
    float mx = fmaxf(v.x, v.y);
#pragma unroll
    for (int o = 16; o; o >>= 1) mx = fmaxf(mx, __shfl_xor_sync(0xFFFFFFFFu, mx, o));
    float e0 = __expf(v.x - mx), e1 = __expf(v.y - mx);
    float s = e0 + e1;
#pragma unroll
    for (int o = 16; o; o >>= 1) s += __shfl_xor_sync(0xFFFFFFFFu, s, o);
    float inv = 1.0f / s;
    *(float2*)(row + lane * 2) = make_float2(e0 * inv, e1 * inv);
}

// ---------------------------------------------------------------------------
// Attention kernel: one block per (b,h).
// Phase 1: kv_sin/kv_cos (64x64 each), ksum_sin/cos (64 each).
// Derived: vsum (column sums of kv), S (sum of ksum) -> complement branch free.
// Phase 2: per row l: t = q @ kv, u = q . ksum, combine both branches.
// Dynamic smem: phase1 k_s(64x64)+v_s(64x64)=32KB; phase2 kv(64x128)+q(128x64)=64KB.
// ---------------------------------------------------------------------------
__global__ __launch_bounds__(256, 1) void attn_kernel()
{
    extern __shared__ float sm[];
    __shared__ float sc_s[64][2];
    __shared__ float ksum_s[2][64];
    __shared__ float vsum_s[128];
    __shared__ float S_s[2];

    const int bh = blockIdx.x;
    const int b = bh >> 4;
    const int h = bh & 15;
    const int tid = threadIdx.x;
    const int tx = tid & 15;
    const int ty = tid >> 4;

    const float* qbase = g_q + ((long long)b * LL) * EE + h * DD;
    const float* kbase = g_k + ((long long)b * LL) * EE + h * DD;
    const float* vbase = g_v + ((long long)b * LL) * EE + h * DD;

    float* k_s = sm;             // [64][64]
    float* v_s = sm + 64 * 64;   // [64][64]

    const float cidx = 1.5707963267948966f / (float)LL;

    float accp[4][8];
#pragma unroll
    for (int i = 0; i < 4; i++)
#pragma unroll
        for (int j = 0; j < 8; j++) accp[i][j] = 0.0f;
    float ks_sin = 0.0f, ks_cos = 0.0f;

    // -------- Phase 1: accumulate kv (64 d-rows x 128 combined cols) --------
    const int mh = (tx & 7) * 8;          // v column base for this thread
    for (int c = 0; c < LL / 64; c++) {
        int l0 = c * 64;
        if (tid < 64) {
            float s, co;
            __sincosf(cidx * (float)(l0 + tid + 1), &s, &co);
            sc_s[tid][0] = s; sc_s[tid][1] = co;
        }
#pragma unroll
        for (int i = 0; i < 4; i++) {
            int idx = tid + i * 256;
            int r  = idx >> 4;    // 0..63
            int c4 = idx & 15;
            *(float4*)&k_s[r * 64 + c4 * 4] = *(const float4*)(kbase + (long long)(l0 + r) * EE + c4 * 4);
            *(float4*)&v_s[r * 64 + c4 * 4] = *(const float4*)(vbase + (long long)(l0 + r) * EE + c4 * 4);
        }
        __syncthreads();
#pragma unroll 4
        for (int l = 0; l < 64; l++) {
            float f = sc_s[l][(tx < 8) ? 0 : 1];
            float ra[4], rv[8];
            *(float4*)&ra[0] = *(const float4*)&k_s[l * 64 + ty * 4];
            *(float4*)&rv[0] = *(const float4*)&v_s[l * 64 + mh];
            *(float4*)&rv[4] = *(const float4*)&v_s[l * 64 + mh + 4];
#pragma unroll
            for (int i = 0; i < 4; i++) {
                float a = ra[i] * f;
#pragma unroll
                for (int j = 0; j < 8; j++)
                    accp[i][j] = fmaf(a, rv[j], accp[i][j]);
            }
        }
        if (tid < 64) {
            for (int l = 0; l < 64; l++) {
                float kd = k_s[l * 64 + tid];
                ks_sin = fmaf(kd, sc_s[l][0], ks_sin);
                ks_cos = fmaf(kd, sc_s[l][1], ks_cos);
            }
        }
        __syncthreads();
    }

    // -------- Stage kv into smem, derive vsum and S --------
    float* kv_s = sm;            // [64][128] (cols 0..63 sin, 64..127 cos)
    float* q_s  = sm + 8192;     // [128][64]
#pragma unroll
    for (int i = 0; i < 4; i++) {
        *(float4*)&kv_s[(ty * 4 + i) * 128 + tx * 8]     = make_float4(accp[i][0], accp[i][1], accp[i][2], accp[i][3]);
        *(float4*)&kv_s[(ty * 4 + i) * 128 + tx * 8 + 4] = make_float4(accp[i][4], accp[i][5], accp[i][6], accp[i][7]);
    }
    if (tid < 64) { ksum_s[0][tid] = ks_sin; ksum_s[1][tid] = ks_cos; }
    __syncthreads();
    if (tid < 128) {
        float s = 0.0f;
        for (int d = 0; d < 64; d++) s += kv_s[d * 128 + tid];
        vsum_s[tid] = s;
    }
    if (tid < 2) {
        float s = 0.0f;
        for (int d = 0; d < 64; d++) s += ksum_s[tid][d];
        S_s[tid] = s;
    }
    __syncthreads();

    const float S_sin = S_s[0], S_cos = S_s[1];

    // -------- Phase 2: per-row outputs, 128 rows per chunk --------
    for (int c = 0; c < LL / 128; c++) {
        int l0 = c * 128;
#pragma unroll
        for (int i = 0; i < 8; i++) {
            int idx = tid + i * 256;
            int r  = idx >> 4;    // 0..127
            int c4 = idx & 15;
            *(float4*)&q_s[r * 64 + c4 * 4] = *(const float4*)(qbase + (long long)(l0 + r) * EE + c4 * 4);
        }
        __syncthreads();

        float ts[8][4], tc2[8][4], us[8], uc[8];
#pragma unroll
        for (int i = 0; i < 8; i++) {
            us[i] = 0.0f; uc[i] = 0.0f;
#pragma unroll
            for (int j = 0; j < 4; j++) { ts[i][j] = 0.0f; tc2[i][j] = 0.0f; }
        }

#pragma unroll 2
        for (int d = 0; d < 64; d++) {
            float rkvs[4], rkvc[4];
            *(float4*)&rkvs[0] = *(const float4*)&kv_s[d * 128 + tx * 4];
            *(float4*)&rkvc[0] = *(const float4*)&kv_s[d * 128 + 64 + tx * 4];
            float kss = ksum_s[0][d], ksc = ksum_s[1][d];
#pragma unroll
            for (int i = 0; i < 8; i++) {
                float qd = q_s[(ty * 8 + i) * 64 + d];
                us[i] = fmaf(qd, kss, us[i]);
                uc[i] = fmaf(qd, ksc, uc[i]);
#pragma unroll
                for (int j = 0; j < 4; j++) {
                    ts[i][j]  = fmaf(qd, rkvs[j], ts[i][j]);
                    tc2[i][j] = fmaf(qd, rkvc[j], tc2[i][j]);
                }
            }
        }

#pragma unroll
        for (int i = 0; i < 8; i++) {
            int l = l0 + ty * 8 + i;
            float s, co;
            __sincosf(cidx * (float)(l + 1), &s, &co);
            float den1 = fmaf(s, us[i], co * uc[i]);
            float z1 = 1.0f / fmaxf(den1, EPSF);
            float den2 = s * (62.0f * S_sin + us[i]) + co * (62.0f * S_cos + uc[i]);
            float z2 = 1.0f / fmaxf(den2, EPSF);
            float tmp[4];
#pragma unroll
            for (int j = 0; j < 4; j++) {
                int m = tx * 4 + j;
                float n1 = fmaf(s, ts[i][j], co * tc2[i][j]);
                float n2 = s * (62.0f * vsum_s[m] + ts[i][j]) + co * (62.0f * vsum_s[64 + m] + tc2[i][j]);
                tmp[j] = n1 * z1 + n2 * z2;
            }
            float* op = g_attn + ((long long)l * BB + b) * EE + h * DD + tx * 4;
            *(float4*)op = make_float4(tmp[0], tmp[1], tmp[2], tmp[3]);
        }
        __syncthreads();
    }
}

// ---------------------------------------------------------------------------
extern "C" void kernel_launch(void* const* d_in, const int* in_sizes, int n_in,
                              void* d_out, int out_size)
{
    (void)in_sizes; (void)n_in; (void)out_size;
    const float* X  = (const float*)d_in[0];
    const float* Wq = (const float*)d_in[1];
    const float* bq = (const float*)d_in[2];
    const float* Wk = (const float*)d_in[3];
    const float* bk = (const float*)d_in[4];
    const float* Wv = (const float*)d_in[5];
    const float* bv = (const float*)d_in[6];
    const float* Wo = (const float*)d_in[7];
    const float* bo = (const float*)d_in[8];
    float* out = (float*)d_out;

    float *gq, *gk, *gv, *ga;
    cudaGetSymbolAddress((void**)&gq, g_q);
    cudaGetSymbolAddress((void**)&gk, g_k);
    cudaGetSymbolAddress((void**)&gv, g_v);
    cudaGetSymbolAddress((void**)&ga, g_attn);

    // 1) fused QKV projections
    sgemm3<<<dim3(EE / BN, MROWS / BM, 3), 256>>>(X, Wq, bq, gq, Wk, bk, gk, Wv, bv, gv);

    // 2) softmax over head dim for q and k (in place)
    {
        long long warps = 2LL * BB * LL * HH;
        int blocks = (int)((warps * 32 + 255) / 256);
        softmax_qk<<<blocks, 256>>>();
    }

    // 3) linear attention per (b,h)
    cudaFuncSetAttribute(attn_kernel, cudaFuncAttributeMaxDynamicSharedMemorySize, 65536);
    attn_kernel<<<BB * HH, 256, 65536>>>();

    // 4) output projection into d_out
    sgemm3<<<dim3(EE / BN, MROWS / BM, 1), 256>>>(ga, Wo, bo, out, Wo, bo, out, Wo, bo, out);
}

// round 2
// speedup vs baseline: 2.6070x; 2.6070x over previous
#include <cuda_runtime.h>
#include <math.h>

// Problem constants
#define BB 8
#define LL 2048
#define EE 1024
#define HH 16
#define DD 64
#define MROWS (BB*LL)          // 16384
#define EPSF 1e-6f

// Scratch (device globals: allocation-free rule)
__device__ float g_q[(size_t)MROWS * EE];
__device__ float g_k[(size_t)MROWS * EE];
__device__ float g_v[(size_t)MROWS * EE];
__device__ float g_attn[(size_t)MROWS * EE];
__device__ float g_xt[(size_t)MROWS * EE];        // tf32-rounded X
__device__ float g_wqt[(size_t)EE * EE];
__device__ float g_wkt[(size_t)EE * EE];
__device__ float g_wvt[(size_t)EE * EE];
__device__ float g_wot[(size_t)EE * EE];

__device__ __forceinline__ float tf32_rna(float x) {
    unsigned u;
    asm("cvt.rna.tf32.f32 %0, %1;" : "=r"(u) : "f"(x));
    return __uint_as_float(u);
}

// ---------------------------------------------------------------------------
// Pre-round inputs to tf32 (round-to-nearest, unbiased) into scratch.
// ---------------------------------------------------------------------------
#define XF4 ((MROWS*EE)/4)   // 4194304
#define WF4 ((EE*EE)/4)      // 262144

__global__ __launch_bounds__(256) void round_inputs(
    const float* __restrict__ X,
    const float* __restrict__ Wq, const float* __restrict__ Wk,
    const float* __restrict__ Wv, const float* __restrict__ Wo)
{
    long long i4 = (long long)blockIdx.x * 256 + threadIdx.x;
    const float* src; float* dst; long long off;
    if (i4 < XF4) { src = X; dst = g_xt; off = i4; }
    else {
        long long r = i4 - XF4;
        int w = (int)(r / WF4);
        off = r % WF4;
        if (w == 0)      { src = Wq; dst = g_wqt; }
        else if (w == 1) { src = Wk; dst = g_wkt; }
        else if (w == 2) { src = Wv; dst = g_wvt; }
        else             { src = Wo; dst = g_wot; }
    }
    float4 v = *(const float4*)(src + off * 4);
    v.x = tf32_rna(v.x); v.y = tf32_rna(v.y);
    v.z = tf32_rna(v.z); v.w = tf32_rna(v.w);
    *(float4*)(dst + off * 4) = v;
}

// ---------------------------------------------------------------------------
// Tensor-core tf32 GEMM: C = A(MxK) @ W(KxN) + bias, row-major.
// Block tile 128x256, BK=32, 256 threads (8 warps, each 64x64).
// mma.sync.m16n8k8 tf32, cp.async double-buffered.
// blockIdx.z selects among up to 3 (W,bias,C) triples (fused QKV).
// ---------------------------------------------------------------------------
#define BM 128
#define BN 256
#define BKC 32
#define SA 36              // A smem row stride (floats), 144B (16B aligned)
#define SB 264             // B smem row stride (floats), 1056B (16B aligned)
#define A_F (BM*SA)        // 4608 floats
#define B_F (BKC*SB)       // 8448 floats
#define STAGE_F (A_F+B_F)  // 13056 floats
#define GSMEM_BYTES (2*STAGE_F*4)   // 104448

__device__ __forceinline__ void cp16(void* dst, const void* src) {
    unsigned d = (unsigned)__cvta_generic_to_shared(dst);
    asm volatile("cp.async.cg.shared.global [%0], [%1], 16;\n" :: "r"(d), "l"(src) : "memory");
}

__global__ __launch_bounds__(256, 1) void gemm_tc(
    const float* __restrict__ A,
    const float* __restrict__ W0, const float* __restrict__ b0, float* __restrict__ C0,
    const float* __restrict__ W1, const float* __restrict__ b1, float* __restrict__ C1,
    const float* __restrict__ W2, const float* __restrict__ b2, float* __restrict__ C2)
{
    constexpr int K = EE;
    constexpr int N = EE;
    const float* Wp = W0; const float* bp = b0; float* Cp = C0;
    if (blockIdx.z == 1) { Wp = W1; bp = b1; Cp = C1; }
    else if (blockIdx.z == 2) { Wp = W2; bp = b2; Cp = C2; }

    extern __shared__ float smp[];

    const int tid = threadIdx.x;
    const int wid = tid >> 5;
    const int lane = tid & 31;
    const int g = lane >> 2;       // groupID 0..7
    const int tg = lane & 3;       // threadID_in_group 0..3
    const int wm = wid & 1;        // 0..1 (M)
    const int wn = wid >> 1;       // 0..3 (N)

    const long long brow = (long long)blockIdx.y * BM;
    const int bcol = blockIdx.x * BN;

    const float* Abase = A + brow * K;
    const float* Wbase = Wp + bcol;

    float acc[4][8][4];
#pragma unroll
    for (int mi = 0; mi < 4; mi++)
#pragma unroll
        for (int ni = 0; ni < 8; ni++)
#pragma unroll
            for (int r = 0; r < 4; r++) acc[mi][ni][r] = 0.0f;

    // ---- stage loader ----
    auto load_stage = [&](int st, int kt) {
        float* As = smp + st * STAGE_F;
        float* Bs = As + A_F;
#pragma unroll
        for (int i = 0; i < 4; i++) {
            int idx = tid + i * 256;
            int m = idx >> 3, ch = idx & 7;
            cp16(As + m * SA + ch * 4, Abase + (long long)m * K + kt + ch * 4);
        }
#pragma unroll
        for (int i = 0; i < 8; i++) {
            int idx = tid + i * 256;
            int kr = idx >> 6, ch = idx & 63;
            cp16(Bs + kr * SB + ch * 4, Wbase + (long long)(kt + kr) * N + ch * 4);
        }
        asm volatile("cp.async.commit_group;\n" ::: "memory");
    };

    const int NC = K / BKC;   // 32
    load_stage(0, 0);

    for (int ct = 0; ct < NC; ct++) {
        int cur = ct & 1;
        if (ct + 1 < NC) {
            load_stage(cur ^ 1, (ct + 1) * BKC);
            asm volatile("cp.async.wait_group 1;\n" ::: "memory");
        } else {
            asm volatile("cp.async.wait_group 0;\n" ::: "memory");
        }
        __syncthreads();

        const float* As = smp + cur * STAGE_F;
        const float* Bs = As + A_F;

#pragma unroll
        for (int ks = 0; ks < 4; ks++) {
            unsigned af[4][4], bf[8][2];
            int k0 = ks * 8 + tg;
#pragma unroll
            for (int mi = 0; mi < 4; mi++) {
                int m = wm * 64 + mi * 16 + g;
                af[mi][0] = __float_as_uint(As[m * SA + k0]);
                af[mi][1] = __float_as_uint(As[(m + 8) * SA + k0]);
                af[mi][2] = __float_as_uint(As[m * SA + k0 + 4]);
                af[mi][3] = __float_as_uint(As[(m + 8) * SA + k0 + 4]);
            }
#pragma unroll
            for (int ni = 0; ni < 8; ni++) {
                int n = wn * 64 + ni * 8 + g;
                bf[ni][0] = __float_as_uint(Bs[k0 * SB + n]);
                bf[ni][1] = __float_as_uint(Bs[(k0 + 4) * SB + n]);
            }
#pragma unroll
            for (int mi = 0; mi < 4; mi++)
#pragma unroll
                for (int ni = 0; ni < 8; ni++) {
                    asm volatile(
                        "mma.sync.aligned.m16n8k8.row.col.f32.tf32.tf32.f32 "
                        "{%0,%1,%2,%3}, {%4,%5,%6,%7}, {%8,%9}, {%0,%1,%2,%3};"
                        : "+f"(acc[mi][ni][0]), "+f"(acc[mi][ni][1]),
                          "+f"(acc[mi][ni][2]), "+f"(acc[mi][ni][3])
                        : "r"(af[mi][0]), "r"(af[mi][1]), "r"(af[mi][2]), "r"(af[mi][3]),
                          "r"(bf[ni][0]), "r"(bf[ni][1]));
                }
        }
        __syncthreads();
    }

    // ---- epilogue: add bias, write ----
#pragma unroll
    for (int ni = 0; ni < 8; ni++) {
        int col = bcol + wn * 64 + ni * 8 + 2 * tg;
        float2 bi = *(const float2*)(bp + col);
#pragma unroll
        for (int mi = 0; mi < 4; mi++) {
            long long r0 = brow + wm * 64 + mi * 16 + g;
            float2 o0, o1;
            o0.x = acc[mi][ni][0] + bi.x; o0.y = acc[mi][ni][1] + bi.y;
            o1.x = acc[mi][ni][2] + bi.x; o1.y = acc[mi][ni][3] + bi.y;
            *(float2*)(Cp + r0 * N + col) = o0;
            *(float2*)(Cp + (r0 + 8) * N + col) = o1;
        }
    }
}

// ---------------------------------------------------------------------------
// Row softmax over D=64 for q and k in place. One warp per 64-float row.
// ---------------------------------------------------------------------------
__global__ __launch_bounds__(256) void softmax_qk()
{
    const long long NR = (long long)BB * LL * HH;     // 262144 rows per tensor
    long long w = (((long long)blockIdx.x * blockDim.x) + threadIdx.x) >> 5;
    int lane = threadIdx.x & 31;
    if (w >= 2 * NR) return;
    float* row = (w < NR) ? (g_q + w * DD) : (g_k + (w - NR) * DD);

    float2 v = *(float2*)(row + lane * 2);
    float mx = fmaxf(v.x, v.y);
#pragma unroll
    for (int o = 16; o; o >>= 1) mx = fmaxf(mx, __shfl_xor_sync(0xFFFFFFFFu, mx, o));
    float e0 = __expf(v.x - mx), e1 = __expf(v.y - mx);
    float s = e0 + e1;
#pragma unroll
    for (int o = 16; o; o >>= 1) s += __shfl_xor_sync(0xFFFFFFFFu, s, o);
    float inv = 1.0f / s;
    *(float2*)(row + lane * 2) = make_float2(e0 * inv, e1 * inv);
}

// ---------------------------------------------------------------------------
// Attention kernel: one block per (b,h). (See Round-1 derivation; complement
// branch collapsed algebraically using softmax row-sum = 1.)
// Output rounded to tf32 (rna) so the Wo tensor-core GEMM stays unbiased.
// ---------------------------------------------------------------------------
__global__ __launch_bounds__(256, 1) void attn_kernel()
{
    extern __shared__ float sm[];
    __shared__ float sc_s[64][2];
    __shared__ float ksum_s[2][64];
    __shared__ float vsum_s[128];
    __shared__ float S_s[2];

    const int bh = blockIdx.x;
    const int b = bh >> 4;
    const int h = bh & 15;
    const int tid = threadIdx.x;
    const int tx = tid & 15;
    const int ty = tid >> 4;

    const float* qbase = g_q + ((long long)b * LL) * EE + h * DD;
    const float* kbase = g_k + ((long long)b * LL) * EE + h * DD;
    const float* vbase = g_v + ((long long)b * LL) * EE + h * DD;

    float* k_s = sm;             // [64][64]
    float* v_s = sm + 64 * 64;   // [64][64]

    const float cidx = 1.5707963267948966f / (float)LL;

    float accp[4][8];
#pragma unroll
    for (int i = 0; i < 4; i++)
#pragma unroll
        for (int j = 0; j < 8; j++) accp[i][j] = 0.0f;
    float ks_sin = 0.0f, ks_cos = 0.0f;

    const int mh = (tx & 7) * 8;
    for (int c = 0; c < LL / 64; c++) {
        int l0 = c * 64;
        if (tid < 64) {
            float s, co;
            __sincosf(cidx * (float)(l0 + tid + 1), &s, &co);
            sc_s[tid][0] = s; sc_s[tid][1] = co;
        }
#pragma unroll
        for (int i = 0; i < 4; i++) {
            int idx = tid + i * 256;
            int r  = idx >> 4;
            int c4 = idx & 15;
            *(float4*)&k_s[r * 64 + c4 * 4] = *(const float4*)(kbase + (long long)(l0 + r) * EE + c4 * 4);
            *(float4*)&v_s[r * 64 + c4 * 4] = *(const float4*)(vbase + (long long)(l0 + r) * EE + c4 * 4);
        }
        __syncthreads();
#pragma unroll 4
        for (int l = 0; l < 64; l++) {
            float f = sc_s[l][(tx < 8) ? 0 : 1];
            float ra[4], rv[8];
            *(float4*)&ra[0] = *(const float4*)&k_s[l * 64 + ty * 4];
            *(float4*)&rv[0] = *(const float4*)&v_s[l * 64 + mh];
            *(float4*)&rv[4] = *(const float4*)&v_s[l * 64 + mh + 4];
#pragma unroll
            for (int i = 0; i < 4; i++) {
                float a = ra[i] * f;
#pragma unroll
                for (int j = 0; j < 8; j++)
                    accp[i][j] = fmaf(a, rv[j], accp[i][j]);
            }
        }
        if (tid < 64) {
            for (int l = 0; l < 64; l++) {
                float kd = k_s[l * 64 + tid];
                ks_sin = fmaf(kd, sc_s[l][0], ks_sin);
                ks_cos = fmaf(kd, sc_s[l][1], ks_cos);
            }
        }
        __syncthreads();
    }

    float* kv_s = sm;            // [64][128]
    float* q_s  = sm + 8192;     // [128][64]
#pragma unroll
    for (int i = 0; i < 4; i++) {
        *(float4*)&kv_s[(ty * 4 + i) * 128 + tx * 8]     = make_float4(accp[i][0], accp[i][1], accp[i][2], accp[i][3]);
        *(float4*)&kv_s[(ty * 4 + i) * 128 + tx * 8 + 4] = make_float4(accp[i][4], accp[i][5], accp[i][6], accp[i][7]);
    }
    if (tid < 64) { ksum_s[0][tid] = ks_sin; ksum_s[1][tid] = ks_cos; }
    __syncthreads();
    if (tid < 128) {
        float s = 0.0f;
        for (int d = 0; d < 64; d++) s += kv_s[d * 128 + tid];
        vsum_s[tid] = s;
    }
    if (tid < 2) {
        float s = 0.0f;
        for (int d = 0; d < 64; d++) s += ksum_s[tid][d];
        S_s[tid] = s;
    }
    __syncthreads();

    const float S_sin = S_s[0], S_cos = S_s[1];

    for (int c = 0; c < LL / 128; c++) {
        int l0 = c * 128;
#pragma unroll
        for (int i = 0; i < 8; i++) {
            int idx = tid + i * 256;
            int r  = idx >> 4;
            int c4 = idx & 15;
            *(float4*)&q_s[r * 64 + c4 * 4] = *(const float4*)(qbase + (long long)(l0 + r) * EE + c4 * 4);
        }
        __syncthreads();

        float ts[8][4], tc2[8][4], us[8], uc[8];
#pragma unroll
        for (int i = 0; i < 8; i++) {
            us[i] = 0.0f; uc[i] = 0.0f;
#pragma unroll
            for (int j = 0; j < 4; j++) { ts[i][j] = 0.0f; tc2[i][j] = 0.0f; }
        }

#pragma unroll 2
        for (int d = 0; d < 64; d++) {
            float rkvs[4], rkvc[4];
            *(float4*)&rkvs[0] = *(const float4*)&kv_s[d * 128 + tx * 4];
            *(float4*)&rkvc[0] = *(const float4*)&kv_s[d * 128 + 64 + tx * 4];
            float kss = ksum_s[0][d], ksc = ksum_s[1][d];
#pragma unroll
            for (int i = 0; i < 8; i++) {
                float qd = q_s[(ty * 8 + i) * 64 + d];
                us[i] = fmaf(qd, kss, us[i]);
                uc[i] = fmaf(qd, ksc, uc[i]);
#pragma unroll
                for (int j = 0; j < 4; j++) {
                    ts[i][j]  = fmaf(qd, rkvs[j], ts[i][j]);
                    tc2[i][j] = fmaf(qd, rkvc[j], tc2[i][j]);
                }
            }
        }

#pragma unroll
        for (int i = 0; i < 8; i++) {
            int l = l0 + ty * 8 + i;
            float s, co;
            __sincosf(cidx * (float)(l + 1), &s, &co);
            float den1 = fmaf(s, us[i], co * uc[i]);
            float z1 = 1.0f / fmaxf(den1, EPSF);
            float den2 = s * (62.0f * S_sin + us[i]) + co * (62.0f * S_cos + uc[i]);
            float z2 = 1.0f / fmaxf(den2, EPSF);
            float tmp[4];
#pragma unroll
            for (int j = 0; j < 4; j++) {
                int m = tx * 4 + j;
                float n1 = fmaf(s, ts[i][j], co * tc2[i][j]);
                float n2 = s * (62.0f * vsum_s[m] + ts[i][j]) + co * (62.0f * vsum_s[64 + m] + tc2[i][j]);
                tmp[j] = tf32_rna(n1 * z1 + n2 * z2);
            }
            float* op = g_attn + ((long long)l * BB + b) * EE + h * DD + tx * 4;
            *(float4*)op = make_float4(tmp[0], tmp[1], tmp[2], tmp[3]);
        }
        __syncthreads();
    }
}

// ---------------------------------------------------------------------------
extern "C" void kernel_launch(void* const* d_in, const int* in_sizes, int n_in,
                              void* d_out, int out_size)
{
    (void)in_sizes; (void)n_in; (void)out_size;
    const float* X  = (const float*)d_in[0];
    const float* Wq = (const float*)d_in[1];
    const float* bq = (const float*)d_in[2];
    const float* Wk = (const float*)d_in[3];
    const float* bk = (const float*)d_in[4];
    const float* Wv = (const float*)d_in[5];
    const float* bv = (const float*)d_in[6];
    const float* Wo = (const float*)d_in[7];
    const float* bo = (const float*)d_in[8];
    float* out = (float*)d_out;

    float *gq, *gk, *gv, *ga, *gxt, *gwq, *gwk, *gwv, *gwo;
    cudaGetSymbolAddress((void**)&gq, g_q);
    cudaGetSymbolAddress((void**)&gk, g_k);
    cudaGetSymbolAddress((void**)&gv, g_v);
    cudaGetSymbolAddress((void**)&ga, g_attn);
    cudaGetSymbolAddress((void**)&gxt, g_xt);
    cudaGetSymbolAddress((void**)&gwq, g_wqt);
    cudaGetSymbolAddress((void**)&gwk, g_wkt);
    cudaGetSymbolAddress((void**)&gwv, g_wvt);
    cudaGetSymbolAddress((void**)&gwo, g_wot);

    cudaFuncSetAttribute(gemm_tc, cudaFuncAttributeMaxDynamicSharedMemorySize, GSMEM_BYTES);
    cudaFuncSetAttribute(attn_kernel, cudaFuncAttributeMaxDynamicSharedMemorySize, 65536);

    // 0) round inputs to tf32 (unbiased) into scratch
    {
        long long tot4 = (long long)XF4 + 4 * WF4;   // 5,242,880
        round_inputs<<<(int)((tot4 + 255) / 256), 256>>>(X, Wq, Wk, Wv, Wo);
    }

    // 1) fused QKV projections (tensor cores)
    gemm_tc<<<dim3(EE / BN, MROWS / BM, 3), 256, GSMEM_BYTES>>>(
        gxt, gwq, bq, gq, gwk, bk, gk, gwv, bv, gv);

    // 2) softmax over head dim for q and k (in place)
    {
        long long warps = 2LL * BB * LL * HH;
        int blocks = (int)((warps * 32 + 255) / 256);
        softmax_qk<<<blocks, 256>>>();
    }

    // 3) linear attention per (b,h)
    attn_kernel<<<BB * HH, 256, 65536>>>();

    // 4) output projection into d_out (tensor cores)
    gemm_tc<<<dim3(EE / BN, MROWS / BM, 1), 256, GSMEM_BYTES>>>(
        ga, gwo, bo, out, gwo, bo, out, gwo, bo, out);
}

// round 8
// speedup vs baseline: 3.3808x; 1.2968x over previous
#include <cuda_runtime.h>
#include <cuda_fp16.h>
#include <math.h>
#include <stdint.h>

// Problem constants
#define BB 8
#define LL 2048
#define EE 1024
#define HH 16
#define DD 64
#define MROWS (BB*LL)          // 16384
#define EPSF 1e-6f

// Scratch (device globals: allocation-free rule)
__device__ float  g_q[(size_t)MROWS * EE];
__device__ float  g_k[(size_t)MROWS * EE];
__device__ float  g_v[(size_t)MROWS * EE];
__device__ __half g_ah[(size_t)MROWS * EE];      // fp16 attention output (Wo GEMM input)
__device__ __half g_xh[(size_t)MROWS * EE];      // fp16 X
__device__ __half g_wqh[(size_t)EE * EE];        // fp16 transposed weights [N][K]
__device__ __half g_wkh[(size_t)EE * EE];
__device__ __half g_wvh[(size_t)EE * EE];
__device__ __half g_woh[(size_t)EE * EE];
#define PSTRIDE 8320                              // 64*128 kv + 2*64 ksum
__device__ float  g_part[512 * PSTRIDE];          // attn phase-1 partials

// ---------------------------------------------------------------------------
// Conversions
// ---------------------------------------------------------------------------
__global__ __launch_bounds__(256) void conv_x(const float* __restrict__ X)
{
    long long i8 = (long long)blockIdx.x * 256 + threadIdx.x;   // 8 floats each
    long long base = i8 * 8;
    if (base >= (long long)MROWS * EE) return;
    float4 v0 = *(const float4*)(X + base);
    float4 v1 = *(const float4*)(X + base + 4);
    __half2 h[4];
    h[0] = __floats2half2_rn(v0.x, v0.y);
    h[1] = __floats2half2_rn(v0.z, v0.w);
    h[2] = __floats2half2_rn(v1.x, v1.y);
    h[3] = __floats2half2_rn(v1.z, v1.w);
    *(uint4*)(g_xh + base) = *(uint4*)h;
}

// Weight transpose + fp16 round: Wt[n][k] = rn(W[k][n]). 32x32 tiles.
__global__ __launch_bounds__(256) void wtrans_h(
    const float* __restrict__ Wq, const float* __restrict__ Wk,
    const float* __restrict__ Wv, const float* __restrict__ Wo)
{
    __shared__ float t[32][33];
    const float* W; __half* Wt;
    switch (blockIdx.z) {
        case 0: W = Wq; Wt = g_wqh; break;
        case 1: W = Wk; Wt = g_wkh; break;
        case 2: W = Wv; Wt = g_wvh; break;
        default: W = Wo; Wt = g_woh; break;
    }
    int tx = threadIdx.x & 31, ty = threadIdx.x >> 5;   // 32 x 8
    int k0 = blockIdx.y * 32, n0 = blockIdx.x * 32;
#pragma unroll
    for (int i = 0; i < 4; i++)
        t[ty + i * 8][tx] = W[(long long)(k0 + ty + i * 8) * EE + n0 + tx];
    __syncthreads();
#pragma unroll
    for (int i = 0; i < 4; i++)
        Wt[(long long)(n0 + ty + i * 8) * EE + k0 + tx] = __float2half_rn(t[tx][ty + i * 8]);
}

// ---------------------------------------------------------------------------
// fp16 tensor-core GEMM: C = A(MxK) @ Wt(NxK)^T + bias, fp32 accum/output.
// CTA tile 128x256, BK=32 halves, 256 threads (8 warps, each 64x64).
// mma.sync.m16n8k16.f32.f16.f16.f32; 3-stage cp.async pipeline.
// Smem pitch 80B/row: fragment LDS provably conflict-free.
// blockIdx.z selects among up to 3 (W,bias,C) triples.
// ---------------------------------------------------------------------------
#define HP 80                     // bytes per smem row
#define ASTG (128*HP)             // 10240
#define BSTG (256*HP)             // 20480
#define STGH (ASTG+BSTG)          // 30720
#define GSMH (3*STGH)             // 92160
#define NCH 32                    // 1024/32 chunks

__device__ __forceinline__ void cp16(void* dst, const void* src) {
    unsigned d = (unsigned)__cvta_generic_to_shared(dst);
    asm volatile("cp.async.cg.shared.global [%0], [%1], 16;\n" :: "r"(d), "l"(src) : "memory");
}

__global__ __launch_bounds__(256, 1) void gemm_h(
    const __half* __restrict__ A,
    const __half* __restrict__ W0, const float* __restrict__ b0, float* __restrict__ C0,
    const __half* __restrict__ W1, const float* __restrict__ b1, float* __restrict__ C1,
    const __half* __restrict__ W2, const float* __restrict__ b2, float* __restrict__ C2)
{
    constexpr int K = EE;
    constexpr int N = EE;
    const __half* Wp = W0; const float* bp = b0; float* Cp = C0;
    if (blockIdx.z == 1) { Wp = W1; bp = b1; Cp = C1; }
    else if (blockIdx.z == 2) { Wp = W2; bp = b2; Cp = C2; }

    extern __shared__ char smc[];

    const int tid = threadIdx.x;
    const int wid = tid >> 5;
    const int lane = tid & 31;
    const int g = lane >> 2;       // 0..7
    const int tg = lane & 3;       // 0..3
    const int wm = wid & 1;
    const int wn = wid >> 1;

    const long long brow = (long long)blockIdx.y * 128;
    const int bcol = blockIdx.x * 256;

    const __half* Abase = A + brow * K;
    const __half* Bbase = Wp + (long long)bcol * K;

    float acc[4][8][4];
#pragma unroll
    for (int mi = 0; mi < 4; mi++)
#pragma unroll
        for (int ni = 0; ni < 8; ni++)
#pragma unroll
            for (int r = 0; r < 4; r++) acc[mi][ni][r] = 0.0f;

    auto load_chunk = [&](int ch) {
        char* As = smc + (ch % 3) * STGH;
        char* Bs = As + ASTG;
        const __half* Ag = Abase + ch * 32;
        const __half* Bg = Bbase + ch * 32;
#pragma unroll
        for (int i = 0; i < 2; i++) {           // A: 128 rows x 4 granules
            int idx = tid + i * 256;
            int r = idx >> 2, c = idx & 3;
            cp16(As + r * HP + c * 16, Ag + (long long)r * K + c * 8);
        }
#pragma unroll
        for (int i = 0; i < 4; i++) {           // B: 256 rows x 4 granules
            int idx = tid + i * 256;
            int r = idx >> 2, c = idx & 3;
            cp16(Bs + r * HP + c * 16, Bg + (long long)r * K + c * 8);
        }
        asm volatile("cp.async.commit_group;\n" ::: "memory");
    };

    load_chunk(0);
    load_chunk(1);

    for (int c = 0; c < NCH; c++) {
        if (c + 2 < NCH) {
            load_chunk(c + 2);
            asm volatile("cp.async.wait_group 2;\n" ::: "memory");
        } else if (c + 1 < NCH) {
            asm volatile("cp.async.wait_group 1;\n" ::: "memory");
        } else {
            asm volatile("cp.async.wait_group 0;\n" ::: "memory");
        }
        __syncthreads();

        const char* As = smc + (c % 3) * STGH;
        const char* Bs = As + ASTG;

#pragma unroll
        for (int s = 0; s < 2; s++) {           // two k16 steps per 32-half chunk
            unsigned af[4][4], bf[8][2];
            int kb = s * 32 + tg * 4;           // byte offset in row
#pragma unroll
            for (int mi = 0; mi < 4; mi++) {
                int m = wm * 64 + mi * 16 + g;
                af[mi][0] = *(const unsigned*)(As + m * HP + kb);
                af[mi][1] = *(const unsigned*)(As + (m + 8) * HP + kb);
                af[mi][2] = *(const unsigned*)(As + m * HP + kb + 16);
                af[mi][3] = *(const unsigned*)(As + (m + 8) * HP + kb + 16);
            }
#pragma unroll
            for (int ni = 0; ni < 8; ni++) {
                int n = wn * 64 + ni * 8 + g;
                bf[ni][0] = *(const unsigned*)(Bs + n * HP + kb);
                bf[ni][1] = *(const unsigned*)(Bs + n * HP + kb + 16);
            }
#pragma unroll
            for (int mi = 0; mi < 4; mi++)
#pragma unroll
                for (int ni = 0; ni < 8; ni++) {
                    asm volatile(
                        "mma.sync.aligned.m16n8k16.row.col.f32.f16.f16.f32 "
                        "{%0,%1,%2,%3}, {%4,%5,%6,%7}, {%8,%9}, {%0,%1,%2,%3};"
                        : "+f"(acc[mi][ni][0]), "+f"(acc[mi][ni][1]),
                          "+f"(acc[mi][ni][2]), "+f"(acc[mi][ni][3])
                        : "r"(af[mi][0]), "r"(af[mi][1]), "r"(af[mi][2]), "r"(af[mi][3]),
                          "r"(bf[ni][0]), "r"(bf[ni][1]));
                }
        }
        __syncthreads();
    }

    // epilogue: add bias, write fp32
#pragma unroll
    for (int ni = 0; ni < 8; ni++) {
        int col = bcol + wn * 64 + ni * 8 + 2 * tg;
        float2 bi = *(const float2*)(bp + col);
#pragma unroll
        for (int mi = 0; mi < 4; mi++) {
            long long r0 = brow + wm * 64 + mi * 16 + g;
            float2 o0, o1;
            o0.x = acc[mi][ni][0] + bi.x; o0.y = acc[mi][ni][1] + bi.y;
            o1.x = acc[mi][ni][2] + bi.x; o1.y = acc[mi][ni][3] + bi.y;
            *(float2*)(Cp + r0 * N + col) = o0;
            *(float2*)(Cp + (r0 + 8) * N + col) = o1;
        }
    }
}

// ---------------------------------------------------------------------------
// Row softmax over D=64 for q and k in place. One warp per 64-float row.
// ---------------------------------------------------------------------------
__global__ __launch_bounds__(256) void softmax_qk()
{
    const long long NR = (long long)BB * LL * HH;     // 262144 rows per tensor
    long long w = (((long long)blockIdx.x * blockDim.x) + threadIdx.x) >> 5;
    int lane = threadIdx.x & 31;
    if (w >= 2 * NR) return;
    float* row = (w < NR) ? (g_q + w * DD) : (g_k + (w - NR) * DD);

    float2 v = *(float2*)(row + lane * 2);
    float mx = fmaxf(v.x, v.y);
#pragma unroll
    for (int o = 16; o; o >>= 1) mx = fmaxf(mx, __shfl_xor_sync(0xFFFFFFFFu, mx, o));
    float e0 = __expf(v.x - mx), e1 = __expf(v.y - mx);
    float s = e0 + e1;
#pragma unroll
    for (int o = 16; o; o >>= 1) s += __shfl_xor_sync(0xFFFFFFFFu, s, o);
    float inv = 1.0f / s;
    *(float2*)(row + lane * 2) = make_float2(e0 * inv, e1 * inv);
}

// ---------------------------------------------------------------------------
// Attention phase 1: partial kv (64x128) + ksum (2x64) per (pair, split).
// grid = 512: blockIdx.x = pair*4 + split; split covers 512 rows.
// ---------------------------------------------------------------------------
__global__ __launch_bounds__(256, 1) void attn_p1()
{
    __shared__ float k_s[64 * 64];
    __shared__ float v_s[64 * 64];
    __shared__ float sc_s[64][2];

    const int bx = blockIdx.x;
    const int pair = bx >> 2;
    const int sp = bx & 3;
    const int b = pair >> 4;
    const int h = pair & 15;
    const int tid = threadIdx.x;
    const int tx = tid & 15;
    const int ty = tid >> 4;

    const float* kbase = g_k + ((long long)b * LL) * EE + h * DD;
    const float* vbase = g_v + ((long long)b * LL) * EE + h * DD;

    const float cidx = 1.5707963267948966f / (float)LL;

    float accp[4][8];
#pragma unroll
    for (int i = 0; i < 4; i++)
#pragma unroll
        for (int j = 0; j < 8; j++) accp[i][j] = 0.0f;
    float ks_sin = 0.0f, ks_cos = 0.0f;

    const int mh = (tx & 7) * 8;
    for (int c = 0; c < 8; c++) {
        int l0 = sp * 512 + c * 64;
        if (tid < 64) {
            float s, co;
            __sincosf(cidx * (float)(l0 + tid + 1), &s, &co);
            sc_s[tid][0] = s; sc_s[tid][1] = co;
        }
#pragma unroll
        for (int i = 0; i < 4; i++) {
            int idx = tid + i * 256;
            int r  = idx >> 4;
            int c4 = idx & 15;
            *(float4*)&k_s[r * 64 + c4 * 4] = *(const float4*)(kbase + (long long)(l0 + r) * EE + c4 * 4);
            *(float4*)&v_s[r * 64 + c4 * 4] = *(const float4*)(vbase + (long long)(l0 + r) * EE + c4 * 4);
        }
        __syncthreads();
#pragma unroll 4
        for (int l = 0; l < 64; l++) {
            float f = sc_s[l][(tx < 8) ? 0 : 1];
            float ra[4], rv[8];
            *(float4*)&ra[0] = *(const float4*)&k_s[l * 64 + ty * 4];
            *(float4*)&rv[0] = *(const float4*)&v_s[l * 64 + mh];
            *(float4*)&rv[4] = *(const float4*)&v_s[l * 64 + mh + 4];
#pragma unroll
            for (int i = 0; i < 4; i++) {
                float a = ra[i] * f;
#pragma unroll
                for (int j = 0; j < 8; j++)
                    accp[i][j] = fmaf(a, rv[j], accp[i][j]);
            }
        }
        if (tid < 64) {
            for (int l = 0; l < 64; l++) {
                float kd = k_s[l * 64 + tid];
                ks_sin = fmaf(kd, sc_s[l][0], ks_sin);
                ks_cos = fmaf(kd, sc_s[l][1], ks_cos);
            }
        }
        __syncthreads();
    }

    float* part = g_part + (long long)bx * PSTRIDE;
#pragma unroll
    for (int i = 0; i < 4; i++) {
        *(float4*)&part[(ty * 4 + i) * 128 + tx * 8]     = make_float4(accp[i][0], accp[i][1], accp[i][2], accp[i][3]);
        *(float4*)&part[(ty * 4 + i) * 128 + tx * 8 + 4] = make_float4(accp[i][4], accp[i][5], accp[i][6], accp[i][7]);
    }
    if (tid < 64) { part[8192 + tid] = ks_sin; part[8256 + tid] = ks_cos; }
}

// ---------------------------------------------------------------------------
// Attention phase 2: reduce 4 partials, then per-row outputs for one 128-row
// chunk. grid = 2048: blockIdx.x = pair*16 + chunk. Output fp16 into g_ah.
// ---------------------------------------------------------------------------
__global__ __launch_bounds__(256, 1) void attn_p2()
{
    extern __shared__ float sm[];
    __shared__ float ksum_s[2][64];
    __shared__ float vsum_s[128];
    __shared__ float S_s[2];

    const int bx = blockIdx.x;
    const int pair = bx >> 4;
    const int ch = bx & 15;
    const int b = pair >> 4;
    const int h = pair & 15;
    const int tid = threadIdx.x;
    const int tx = tid & 15;
    const int ty = tid >> 4;

    float* kv_s = sm;            // [64][128]
    float* q_s  = sm + 8192;     // [128][64]

    const float* p0 = g_part + (long long)(pair * 4 + 0) * PSTRIDE;
    const float* p1 = g_part + (long long)(pair * 4 + 1) * PSTRIDE;
    const float* p2 = g_part + (long long)(pair * 4 + 2) * PSTRIDE;
    const float* p3 = g_part + (long long)(pair * 4 + 3) * PSTRIDE;

    // reduce kv partials
    for (int t = tid; t < 2048; t += 256) {
        float4 a = *(const float4*)(p0 + t * 4);
        float4 bq = *(const float4*)(p1 + t * 4);
        float4 cq = *(const float4*)(p2 + t * 4);
        float4 dq = *(const float4*)(p3 + t * 4);
        float4 o;
        o.x = a.x + bq.x + cq.x + dq.x;
        o.y = a.y + bq.y + cq.y + dq.y;
        o.z = a.z + bq.z + cq.z + dq.z;
        o.w = a.w + bq.w + cq.w + dq.w;
        *(float4*)&kv_s[t * 4] = o;
    }
    if (tid < 128) {
        float s = p0[8192 + tid] + p1[8192 + tid] + p2[8192 + tid] + p3[8192 + tid];
        ksum_s[tid >> 6][tid & 63] = s;
    }
    __syncthreads();
    if (tid < 128) {
        float s = 0.0f;
        for (int d = 0; d < 64; d++) s += kv_s[d * 128 + tid];
        vsum_s[tid] = s;
    }
    if (tid < 2) {
        float s = 0.0f;
        for (int d = 0; d < 64; d++) s += ksum_s[tid][d];
        S_s[tid] = s;
    }

    // load q chunk
    const float* qbase = g_q + ((long long)b * LL) * EE + h * DD;
    const int l0 = ch * 128;
#pragma unroll
    for (int i = 0; i < 8; i++) {
        int idx = tid + i * 256;
        int r  = idx >> 4;
        int c4 = idx & 15;
        *(float4*)&q_s[r * 64 + c4 * 4] = *(const float4*)(qbase + (long long)(l0 + r) * EE + c4 * 4);
    }
    __syncthreads();

    const float S_sin = S_s[0], S_cos = S_s[1];
    const float cidx = 1.5707963267948966f / (float)LL;

    float ts[8][4], tc2[8][4], us[8], uc[8];
#pragma unroll
    for (int i = 0; i < 8; i++) {
        us[i] = 0.0f; uc[i] = 0.0f;
#pragma unroll
        for (int j = 0; j < 4; j++) { ts[i][j] = 0.0f; tc2[i][j] = 0.0f; }
    }

#pragma unroll 2
    for (int d = 0; d < 64; d++) {
        float rkvs[4], rkvc[4];
        *(float4*)&rkvs[0] = *(const float4*)&kv_s[d * 128 + tx * 4];
        *(float4*)&rkvc[0] = *(const float4*)&kv_s[d * 128 + 64 + tx * 4];
        float kss = ksum_s[0][d], ksc = ksum_s[1][d];
#pragma unroll
        for (int i = 0; i < 8; i++) {
            float qd = q_s[(ty * 8 + i) * 64 + d];
            us[i] = fmaf(qd, kss, us[i]);
            uc[i] = fmaf(qd, ksc, uc[i]);
#pragma unroll
            for (int j = 0; j < 4; j++) {
                ts[i][j]  = fmaf(qd, rkvs[j], ts[i][j]);
                tc2[i][j] = fmaf(qd, rkvc[j], tc2[i][j]);
            }
        }
    }

#pragma unroll
    for (int i = 0; i < 8; i++) {
        int l = l0 + ty * 8 + i;
        float s, co;
        __sincosf(cidx * (float)(l + 1), &s, &co);
        float den1 = fmaf(s, us[i], co * uc[i]);
        float z1 = 1.0f / fmaxf(den1, EPSF);
        float den2 = s * (62.0f * S_sin + us[i]) + co * (62.0f * S_cos + uc[i]);
        float z2 = 1.0f / fmaxf(den2, EPSF);
        float tmp[4];
#pragma unroll
        for (int j = 0; j < 4; j++) {
            int m = tx * 4 + j;
            float n1 = fmaf(s, ts[i][j], co * tc2[i][j]);
            float n2 = s * (62.0f * vsum_s[m] + ts[i][j]) + co * (62.0f * vsum_s[64 + m] + tc2[i][j]);
            tmp[j] = n1 * z1 + n2 * z2;
        }
        __half2 h01 = __floats2half2_rn(tmp[0], tmp[1]);
        __half2 h23 = __floats2half2_rn(tmp[2], tmp[3]);
        __half* op = g_ah + ((long long)l * BB + b) * EE + h * DD + tx * 4;
        uint2 pk;
        pk.x = *(unsigned*)&h01;
        pk.y = *(unsigned*)&h23;
        *(uint2*)op = pk;
    }
}

// ---------------------------------------------------------------------------
extern "C" void kernel_launch(void* const* d_in, const int* in_sizes, int n_in,
                              void* d_out, int out_size)
{
    (void)in_sizes; (void)n_in; (void)out_size;
    const float* X  = (const float*)d_in[0];
    const float* Wq = (const float*)d_in[1];
    const float* bq = (const float*)d_in[2];
    const float* Wk = (const float*)d_in[3];
    const float* bk = (const float*)d_in[4];
    const float* Wv = (const float*)d_in[5];
    const float* bv = (const float*)d_in[6];
    const float* Wo = (const float*)d_in[7];
    const float* bo = (const float*)d_in[8];
    float* out = (float*)d_out;

    float *gq, *gk, *gv;
    __half *gah, *gxh, *gwq, *gwk, *gwv, *gwo;
    cudaGetSymbolAddress((void**)&gq, g_q);
    cudaGetSymbolAddress((void**)&gk, g_k);
    cudaGetSymbolAddress((void**)&gv, g_v);
    cudaGetSymbolAddress((void**)&gah, g_ah);
    cudaGetSymbolAddress((void**)&gxh, g_xh);
    cudaGetSymbolAddress((void**)&gwq, g_wqh);
    cudaGetSymbolAddress((void**)&gwk, g_wkh);
    cudaGetSymbolAddress((void**)&gwv, g_wvh);
    cudaGetSymbolAddress((void**)&gwo, g_woh);

    cudaFuncSetAttribute(gemm_h, cudaFuncAttributeMaxDynamicSharedMemorySize, GSMH);
    cudaFuncSetAttribute(attn_p2, cudaFuncAttributeMaxDynamicSharedMemorySize, 65536);

    // 0) convert X and weights (transposed) to fp16
    conv_x<<<(int)(((long long)MROWS * EE / 8 + 255) / 256), 256>>>(X);
    wtrans_h<<<dim3(32, 32, 4), 256>>>(Wq, Wk, Wv, Wo);

    // 1) fused QKV projections (fp16 tensor cores, fp32 accum)
    gemm_h<<<dim3(EE / 256, MROWS / 128, 3), 256, GSMH>>>(
        gxh, gwq, bq, gq, gwk, bk, gk, gwv, bv, gv);

    // 2) softmax over head dim for q and k (in place, fp32)
    {
        long long warps = 2LL * BB * LL * HH;
        int blocks = (int)((warps * 32 + 255) / 256);
        softmax_qk<<<blocks, 256>>>();
    }

    // 3) linear attention: split phase 1 / phase 2 for occupancy
    attn_p1<<<512, 256>>>();
    attn_p2<<<2048, 256, 65536>>>();

    // 4) output projection into d_out (fp16 tensor cores)
    gemm_h<<<dim3(EE / 256, MROWS / 128, 1), 256, GSMH>>>(
        gah, gwo, bo, out, gwo, bo, out, gwo, bo, out);
}

// round 10
// speedup vs baseline: 3.5408x; 1.0473x over previous
#include <cuda_runtime.h>
#include <cuda_fp16.h>
#include <math.h>
#include <stdint.h>

// Problem constants
#define BB 8
#define LL 2048
#define EE 1024
#define HH 16
#define DD 64
#define MROWS (BB*LL)          // 16384
#define EPSF 1e-6f

// Scratch (device globals: allocation-free rule)
__device__ float  g_q[(size_t)MROWS * EE];
__device__ float  g_k[(size_t)MROWS * EE];
__device__ float  g_v[(size_t)MROWS * EE];
__device__ __half g_ah[(size_t)MROWS * EE];      // fp16 attention output (Wo GEMM input)
__device__ __half g_xh[(size_t)MROWS * EE];      // fp16 X
__device__ __half g_wqh[(size_t)EE * EE];        // fp16 transposed weights [N][K]
__device__ __half g_wkh[(size_t)EE * EE];
__device__ __half g_wvh[(size_t)EE * EE];
__device__ __half g_woh[(size_t)EE * EE];
#define PSTRIDE 8320                              // 64*128 kv + 2*64 ksum
__device__ float  g_part[512 * PSTRIDE];          // attn phase-1 partials

// ---------------------------------------------------------------------------
// Conversions
// ---------------------------------------------------------------------------
__global__ __launch_bounds__(256) void conv_x(const float* __restrict__ X)
{
    long long i8 = (long long)blockIdx.x * 256 + threadIdx.x;   // 8 floats each
    long long base = i8 * 8;
    if (base >= (long long)MROWS * EE) return;
    float4 v0 = *(const float4*)(X + base);
    float4 v1 = *(const float4*)(X + base + 4);
    __half2 h[4];
    h[0] = __floats2half2_rn(v0.x, v0.y);
    h[1] = __floats2half2_rn(v0.z, v0.w);
    h[2] = __floats2half2_rn(v1.x, v1.y);
    h[3] = __floats2half2_rn(v1.z, v1.w);
    *(uint4*)(g_xh + base) = *(uint4*)h;
}

// Weight transpose + fp16 round: Wt[n][k] = rn(W[k][n]). 32x32 tiles.
__global__ __launch_bounds__(256) void wtrans_h(
    const float* __restrict__ Wq, const float* __restrict__ Wk,
    const float* __restrict__ Wv, const float* __restrict__ Wo)
{
    __shared__ float t[32][33];
    const float* W; __half* Wt;
    switch (blockIdx.z) {
        case 0: W = Wq; Wt = g_wqh; break;
        case 1: W = Wk; Wt = g_wkh; break;
        case 2: W = Wv; Wt = g_wvh; break;
        default: W = Wo; Wt = g_woh; break;
    }
    int tx = threadIdx.x & 31, ty = threadIdx.x >> 5;   // 32 x 8
    int k0 = blockIdx.y * 32, n0 = blockIdx.x * 32;
#pragma unroll
    for (int i = 0; i < 4; i++)
        t[ty + i * 8][tx] = W[(long long)(k0 + ty + i * 8) * EE + n0 + tx];
    __syncthreads();
#pragma unroll
    for (int i = 0; i < 4; i++)
        Wt[(long long)(n0 + ty + i * 8) * EE + k0 + tx] = __float2half_rn(t[tx][ty + i * 8]);
}

// ---------------------------------------------------------------------------
// fp16 tensor-core GEMM: C = A(MxK) @ Wt(NxK)^T + bias, fp32 accum/output.
// CTA tile 128x256, BK=32 halves, 256 threads (8 warps, each 64x64).
// mma.sync.m16n8k16.f32.f16.f16.f32; 3-stage cp.async pipeline, ONE barrier
// per chunk (wait_group -> sync -> issue next load -> mma).
// smask bit z: apply per-head row softmax (D=64) in the epilogue. Each warp's
// 64-col tile is one head; a row is owned by a lane-quad -> shfl reductions.
// ---------------------------------------------------------------------------
#define HP 80                     // bytes per smem row
#define ASTG (128*HP)             // 10240
#define BSTG (256*HP)             // 20480
#define STGH (ASTG+BSTG)          // 30720
#define GSMH (3*STGH)             // 92160
#define NCH 32                    // 1024/32 chunks

__device__ __forceinline__ void cp16(void* dst, const void* src) {
    unsigned d = (unsigned)__cvta_generic_to_shared(dst);
    asm volatile("cp.async.cg.shared.global [%0], [%1], 16;\n" :: "r"(d), "l"(src) : "memory");
}

__global__ __launch_bounds__(256, 1) void gemm_h(
    const __half* __restrict__ A,
    const __half* __restrict__ W0, const float* __restrict__ b0, float* __restrict__ C0,
    const __half* __restrict__ W1, const float* __restrict__ b1, float* __restrict__ C1,
    const __half* __restrict__ W2, const float* __restrict__ b2, float* __restrict__ C2,
    int smask)
{
    constexpr int K = EE;
    constexpr int N = EE;
    const __half* Wp = W0; const float* bp = b0; float* Cp = C0;
    if (blockIdx.z == 1) { Wp = W1; bp = b1; Cp = C1; }
    else if (blockIdx.z == 2) { Wp = W2; bp = b2; Cp = C2; }
    const bool do_sm = (smask >> blockIdx.z) & 1;

    extern __shared__ char smc[];

    const int tid = threadIdx.x;
    const int wid = tid >> 5;
    const int lane = tid & 31;
    const int g = lane >> 2;       // 0..7
    const int tg = lane & 3;       // 0..3
    const int wm = wid & 1;
    const int wn = wid >> 1;

    const long long brow = (long long)blockIdx.y * 128;
    const int bcol = blockIdx.x * 256;

    const __half* Abase = A + brow * K;
    const __half* Bbase = Wp + (long long)bcol * K;

    float acc[4][8][4];
#pragma unroll
    for (int mi = 0; mi < 4; mi++)
#pragma unroll
        for (int ni = 0; ni < 8; ni++)
#pragma unroll
            for (int r = 0; r < 4; r++) acc[mi][ni][r] = 0.0f;

    auto load_chunk = [&](int ch) {
        char* As = smc + (ch % 3) * STGH;
        char* Bs = As + ASTG;
        const __half* Ag = Abase + ch * 32;
        const __half* Bg = Bbase + ch * 32;
#pragma unroll
        for (int i = 0; i < 2; i++) {           // A: 128 rows x 4 granules
            int idx = tid + i * 256;
            int r = idx >> 2, c = idx & 3;
            cp16(As + r * HP + c * 16, Ag + (long long)r * K + c * 8);
        }
#pragma unroll
        for (int i = 0; i < 4; i++) {           // B: 256 rows x 4 granules
            int idx = tid + i * 256;
            int r = idx >> 2, c = idx & 3;
            cp16(Bs + r * HP + c * 16, Bg + (long long)r * K + c * 8);
        }
        asm volatile("cp.async.commit_group;\n" ::: "memory");
    };

    load_chunk(0);
    load_chunk(1);

    for (int c = 0; c < NCH; c++) {
        if (c + 1 < NCH) asm volatile("cp.async.wait_group 1;\n" ::: "memory");
        else             asm volatile("cp.async.wait_group 0;\n" ::: "memory");
        __syncthreads();
        // Safe to overwrite stage (c+2)%3 == (c-1)%3: the barrier above proves
        // every warp finished its mma reads of chunk c-1 (issued last iter).
        if (c + 2 < NCH) load_chunk(c + 2);

        const char* As = smc + (c % 3) * STGH;
        const char* Bs = As + ASTG;

#pragma unroll
        for (int s = 0; s < 2; s++) {           // two k16 steps per 32-half chunk
            unsigned af[4][4], bf[8][2];
            int kb = s * 32 + tg * 4;           // byte offset in row
#pragma unroll
            for (int mi = 0; mi < 4; mi++) {
                int m = wm * 64 + mi * 16 + g;
                af[mi][0] = *(const unsigned*)(As + m * HP + kb);
                af[mi][1] = *(const unsigned*)(As + (m + 8) * HP + kb);
                af[mi][2] = *(const unsigned*)(As + m * HP + kb + 16);
                af[mi][3] = *(const unsigned*)(As + (m + 8) * HP + kb + 16);
            }
#pragma unroll
            for (int ni = 0; ni < 8; ni++) {
                int n = wn * 64 + ni * 8 + g;
                bf[ni][0] = *(const unsigned*)(Bs + n * HP + kb);
                bf[ni][1] = *(const unsigned*)(Bs + n * HP + kb + 16);
            }
#pragma unroll
            for (int mi = 0; mi < 4; mi++)
#pragma unroll
                for (int ni = 0; ni < 8; ni++) {
                    asm volatile(
                        "mma.sync.aligned.m16n8k16.row.col.f32.f16.f16.f32 "
                        "{%0,%1,%2,%3}, {%4,%5,%6,%7}, {%8,%9}, {%0,%1,%2,%3};"
                        : "+f"(acc[mi][ni][0]), "+f"(acc[mi][ni][1]),
                          "+f"(acc[mi][ni][2]), "+f"(acc[mi][ni][3])
                        : "r"(af[mi][0]), "r"(af[mi][1]), "r"(af[mi][2]), "r"(af[mi][3]),
                          "r"(bf[ni][0]), "r"(bf[ni][1]));
                }
        }
    }

    // ---- epilogue: bias (+ optional per-head row softmax), write fp32 ----
    float2 bi[8];
#pragma unroll
    for (int ni = 0; ni < 8; ni++)
        bi[ni] = *(const float2*)(bp + bcol + wn * 64 + ni * 8 + 2 * tg);
#pragma unroll
    for (int mi = 0; mi < 4; mi++)
#pragma unroll
        for (int ni = 0; ni < 8; ni++) {
            acc[mi][ni][0] += bi[ni].x; acc[mi][ni][1] += bi[ni].y;
            acc[mi][ni][2] += bi[ni].x; acc[mi][ni][3] += bi[ni].y;
        }

    if (do_sm) {
        // Row softmax over the warp's 64 cols (= one head). Row owned by the
        // lane-quad g*4+{0..3}; shfl_xor 1,2 stay inside the quad.
#pragma unroll
        for (int mi = 0; mi < 4; mi++)
#pragma unroll
            for (int hf = 0; hf < 2; hf++) {
                float mx = -1e30f;
#pragma unroll
                for (int ni = 0; ni < 8; ni++)
                    mx = fmaxf(mx, fmaxf(acc[mi][ni][hf * 2], acc[mi][ni][hf * 2 + 1]));
                mx = fmaxf(mx, __shfl_xor_sync(0xFFFFFFFFu, mx, 1));
                mx = fmaxf(mx, __shfl_xor_sync(0xFFFFFFFFu, mx, 2));
                float sum = 0.0f;
#pragma unroll
                for (int ni = 0; ni < 8; ni++) {
                    float e0 = __expf(acc[mi][ni][hf * 2]     - mx);
                    float e1 = __expf(acc[mi][ni][hf * 2 + 1] - mx);
                    acc[mi][ni][hf * 2] = e0; acc[mi][ni][hf * 2 + 1] = e1;
                    sum += e0 + e1;
                }
                sum += __shfl_xor_sync(0xFFFFFFFFu, sum, 1);
                sum += __shfl_xor_sync(0xFFFFFFFFu, sum, 2);
                float inv = 1.0f / sum;
#pragma unroll
                for (int ni = 0; ni < 8; ni++) {
                    acc[mi][ni][hf * 2] *= inv; acc[mi][ni][hf * 2 + 1] *= inv;
                }
            }
    }

#pragma unroll
    for (int ni = 0; ni < 8; ni++) {
        int col = bcol + wn * 64 + ni * 8 + 2 * tg;
#pragma unroll
        for (int mi = 0; mi < 4; mi++) {
            long long r0 = brow + wm * 64 + mi * 16 + g;
            *(float2*)(Cp + r0 * N + col)       = make_float2(acc[mi][ni][0], acc[mi][ni][1]);
            *(float2*)(Cp + (r0 + 8) * N + col) = make_float2(acc[mi][ni][2], acc[mi][ni][3]);
        }
    }
}

// ---------------------------------------------------------------------------
// Attention phase 1: partial kv (64x128) + ksum (2x64) per (pair, split).
// grid = 512: blockIdx.x = pair*4 + split; split covers 512 rows.
// ---------------------------------------------------------------------------
__global__ __launch_bounds__(256, 1) void attn_p1()
{
    __shared__ float k_s[64 * 64];
    __shared__ float v_s[64 * 64];
    __shared__ float sc_s[64][2];

    const int bx = blockIdx.x;
    const int pair = bx >> 2;
    const int sp = bx & 3;
    const int b = pair >> 4;
    const int h = pair & 15;
    const int tid = threadIdx.x;
    const int tx = tid & 15;
    const int ty = tid >> 4;

    const float* kbase = g_k + ((long long)b * LL) * EE + h * DD;
    const float* vbase = g_v + ((long long)b * LL) * EE + h * DD;

    const float cidx = 1.5707963267948966f / (float)LL;

    float accp[4][8];
#pragma unroll
    for (int i = 0; i < 4; i++)
#pragma unroll
        for (int j = 0; j < 8; j++) accp[i][j] = 0.0f;
    float ks_sin = 0.0f, ks_cos = 0.0f;

    const int mh = (tx & 7) * 8;
    for (int c = 0; c < 8; c++) {
        int l0 = sp * 512 + c * 64;
        if (tid < 64) {
            float s, co;
            __sincosf(cidx * (float)(l0 + tid + 1), &s, &co);
            sc_s[tid][0] = s; sc_s[tid][1] = co;
        }
#pragma unroll
        for (int i = 0; i < 4; i++) {
            int idx = tid + i * 256;
            int r  = idx >> 4;
            int c4 = idx & 15;
            *(float4*)&k_s[r * 64 + c4 * 4] = *(const float4*)(kbase + (long long)(l0 + r) * EE + c4 * 4);
            *(float4*)&v_s[r * 64 + c4 * 4] = *(const float4*)(vbase + (long long)(l0 + r) * EE + c4 * 4);
        }
        __syncthreads();
#pragma unroll 4
        for (int l = 0; l < 64; l++) {
            float f = sc_s[l][(tx < 8) ? 0 : 1];
            float ra[4], rv[8];
            *(float4*)&ra[0] = *(const float4*)&k_s[l * 64 + ty * 4];
            *(float4*)&rv[0] = *(const float4*)&v_s[l * 64 + mh];
            *(float4*)&rv[4] = *(const float4*)&v_s[l * 64 + mh + 4];
#pragma unroll
            for (int i = 0; i < 4; i++) {
                float a = ra[i] * f;
#pragma unroll
                for (int j = 0; j < 8; j++)
                    accp[i][j] = fmaf(a, rv[j], accp[i][j]);
            }
        }
        if (tid < 64) {
            for (int l = 0; l < 64; l++) {
                float kd = k_s[l * 64 + tid];
                ks_sin = fmaf(kd, sc_s[l][0], ks_sin);
                ks_cos = fmaf(kd, sc_s[l][1], ks_cos);
            }
        }
        __syncthreads();
    }

    float* part = g_part + (long long)bx * PSTRIDE;
#pragma unroll
    for (int i = 0; i < 4; i++) {
        *(float4*)&part[(ty * 4 + i) * 128 + tx * 8]     = make_float4(accp[i][0], accp[i][1], accp[i][2], accp[i][3]);
        *(float4*)&part[(ty * 4 + i) * 128 + tx * 8 + 4] = make_float4(accp[i][4], accp[i][5], accp[i][6], accp[i][7]);
    }
    if (tid < 64) { part[8192 + tid] = ks_sin; part[8256 + tid] = ks_cos; }
}

// ---------------------------------------------------------------------------
// Attention phase 2: reduce 4 partials, then per-row outputs for one 128-row
// chunk. grid = 2048: blockIdx.x = pair*16 + chunk. Output fp16 into g_ah.
// ---------------------------------------------------------------------------
__global__ __launch_bounds__(256, 1) void attn_p2()
{
    extern __shared__ float sm[];
    __shared__ float ksum_s[2][64];
    __shared__ float vsum_s[128];
    __shared__ float S_s[2];

    const int bx = blockIdx.x;
    const int pair = bx >> 4;
    const int ch = bx & 15;
    const int b = pair >> 4;
    const int h = pair & 15;
    const int tid = threadIdx.x;
    const int tx = tid & 15;
    const int ty = tid >> 4;

    float* kv_s = sm;            // [64][128]
    float* q_s  = sm + 8192;     // [128][64]

    const float* p0 = g_part + (long long)(pair * 4 + 0) * PSTRIDE;
    const float* p1 = g_part + (long long)(pair * 4 + 1) * PSTRIDE;
    const float* p2 = g_part + (long long)(pair * 4 + 2) * PSTRIDE;
    const float* p3 = g_part + (long long)(pair * 4 + 3) * PSTRIDE;

    // reduce kv partials
    for (int t = tid; t < 2048; t += 256) {
        float4 a = *(const float4*)(p0 + t * 4);
        float4 bq = *(const float4*)(p1 + t * 4);
        float4 cq = *(const float4*)(p2 + t * 4);
        float4 dq = *(const float4*)(p3 + t * 4);
        float4 o;
        o.x = a.x + bq.x + cq.x + dq.x;
        o.y = a.y + bq.y + cq.y + dq.y;
        o.z = a.z + bq.z + cq.z + dq.z;
        o.w = a.w + bq.w + cq.w + dq.w;
        *(float4*)&kv_s[t * 4] = o;
    }
    if (tid < 128) {
        float s = p0[8192 + tid] + p1[8192 + tid] + p2[8192 + tid] + p3[8192 + tid];
        ksum_s[tid >> 6][tid & 63] = s;
    }
    __syncthreads();
    if (tid < 128) {
        float s = 0.0f;
        for (int d = 0; d < 64; d++) s += kv_s[d * 128 + tid];
        vsum_s[tid] = s;
    }
    if (tid < 2) {
        float s = 0.0f;
        for (int d = 0; d < 64; d++) s += ksum_s[tid][d];
        S_s[tid] = s;
    }

    // load q chunk
    const float* qbase = g_q + ((long long)b * LL) * EE + h * DD;
    const int l0 = ch * 128;
#pragma unroll
    for (int i = 0; i < 8; i++) {
        int idx = tid + i * 256;
        int r  = idx >> 4;
        int c4 = idx & 15;
        *(float4*)&q_s[r * 64 + c4 * 4] = *(const float4*)(qbase + (long long)(l0 + r) * EE + c4 * 4);
    }
    __syncthreads();

    const float S_sin = S_s[0], S_cos = S_s[1];
    const float cidx = 1.5707963267948966f / (float)LL;

    float ts[8][4], tc2[8][4], us[8], uc[8];
#pragma unroll
    for (int i = 0; i < 8; i++) {
        us[i] = 0.0f; uc[i] = 0.0f;
#pragma unroll
        for (int j = 0; j < 4; j++) { ts[i][j] = 0.0f; tc2[i][j] = 0.0f; }
    }

#pragma unroll 2
    for (int d = 0; d < 64; d++) {
        float rkvs[4], rkvc[4];
        *(float4*)&rkvs[0] = *(const float4*)&kv_s[d * 128 + tx * 4];
        *(float4*)&rkvc[0] = *(const float4*)&kv_s[d * 128 + 64 + tx * 4];
        float kss = ksum_s[0][d], ksc = ksum_s[1][d];
#pragma unroll
        for (int i = 0; i < 8; i++) {
            float qd = q_s[(ty * 8 + i) * 64 + d];
            us[i] = fmaf(qd, kss, us[i]);
            uc[i] = fmaf(qd, ksc, uc[i]);
#pragma unroll
            for (int j = 0; j < 4; j++) {
                ts[i][j]  = fmaf(qd, rkvs[j], ts[i][j]);
                tc2[i][j] = fmaf(qd, rkvc[j], tc2[i][j]);
            }
        }
    }

#pragma unroll
    for (int i = 0; i < 8; i++) {
        int l = l0 + ty * 8 + i;
        float s, co;
        __sincosf(cidx * (float)(l + 1), &s, &co);
        float den1 = fmaf(s, us[i], co * uc[i]);
        float z1 = 1.0f / fmaxf(den1, EPSF);
        float den2 = s * (62.0f * S_sin + us[i]) + co * (62.0f * S_cos + uc[i]);
        float z2 = 1.0f / fmaxf(den2, EPSF);
        float tmp[4];
#pragma unroll
        for (int j = 0; j < 4; j++) {
            int m = tx * 4 + j;
            float n1 = fmaf(s, ts[i][j], co * tc2[i][j]);
            float n2 = s * (62.0f * vsum_s[m] + ts[i][j]) + co * (62.0f * vsum_s[64 + m] + tc2[i][j]);
            tmp[j] = n1 * z1 + n2 * z2;
        }
        __half2 h01 = __floats2half2_rn(tmp[0], tmp[1]);
        __half2 h23 = __floats2half2_rn(tmp[2], tmp[3]);
        __half* op = g_ah + ((long long)l * BB + b) * EE + h * DD + tx * 4;
        uint2 pk;
        pk.x = *(unsigned*)&h01;
        pk.y = *(unsigned*)&h23;
        *(uint2*)op = pk;
    }
}

// ---------------------------------------------------------------------------
extern "C" void kernel_launch(void* const* d_in, const int* in_sizes, int n_in,
                              void* d_out, int out_size)
{
    (void)in_sizes; (void)n_in; (void)out_size;
    const float* X  = (const float*)d_in[0];
    const float* Wq = (const float*)d_in[1];
    const float* bq = (const float*)d_in[2];
    const float* Wk = (const float*)d_in[3];
    const float* bk = (const float*)d_in[4];
    const float* Wv = (const float*)d_in[5];
    const float* bv = (const float*)d_in[6];
    const float* Wo = (const float*)d_in[7];
    const float* bo = (const float*)d_in[8];
    float* out = (float*)d_out;

    float *gq, *gk, *gv;
    __half *gah, *gxh, *gwq, *gwk, *gwv, *gwo;
    cudaGetSymbolAddress((void**)&gq, g_q);
    cudaGetSymbolAddress((void**)&gk, g_k);
    cudaGetSymbolAddress((void**)&gv, g_v);
    cudaGetSymbolAddress((void**)&gah, g_ah);
    cudaGetSymbolAddress((void**)&gxh, g_xh);
    cudaGetSymbolAddress((void**)&gwq, g_wqh);
    cudaGetSymbolAddress((void**)&gwk, g_wkh);
    cudaGetSymbolAddress((void**)&gwv, g_wvh);
    cudaGetSymbolAddress((void**)&gwo, g_woh);

    cudaFuncSetAttribute(gemm_h, cudaFuncAttributeMaxDynamicSharedMemorySize, GSMH);
    cudaFuncSetAttribute(attn_p2, cudaFuncAttributeMaxDynamicSharedMemorySize, 65536);

    // 0) convert X and weights (transposed) to fp16
    conv_x<<<(int)(((long long)MROWS * EE / 8 + 255) / 256), 256>>>(X);
    wtrans_h<<<dim3(32, 32, 4), 256>>>(Wq, Wk, Wv, Wo);

    // 1) fused QKV projections with per-head softmax on q,k in the epilogue
    gemm_h<<<dim3(EE / 256, MROWS / 128, 3), 256, GSMH>>>(
        gxh, gwq, bq, gq, gwk, bk, gk, gwv, bv, gv, 0b011);

    // 2) linear attention: split phase 1 / phase 2 for occupancy
    attn_p1<<<512, 256>>>();
    attn_p2<<<2048, 256, 65536>>>();

    // 3) output projection into d_out (fp16 tensor cores)
    gemm_h<<<dim3(EE / 256, MROWS / 128, 1), 256, GSMH>>>(
        gah, gwo, bo, out, gwo, bo, out, gwo, bo, out, 0);
}